// round 16
// baseline (speedup 1.0000x reference)
#include <cuda_runtime.h>
#include <math.h>

#define N_ROWS   16384
#define ACTIONS  64
#define EMB      32
#define DELTA    16
#define EPSF     1e-5f

#define NB1      128                     // bn_partial blocks
#define ROWS_PER_B1 (N_ROWS / NB1)       // 128

#define A_PER_B  4                       // actions per spline block
#define R_PER_B  256                     // rows per spline block (v5 geometry)
#define NBINS    33                      // staged bins (bl 0..31, bh needs +1)

// Scratch: BN partial sums (no allocation allowed in kernel_launch).
__device__ float g_psum[NB1][ACTIONS];
__device__ float g_psq [NB1][ACTIONS];

// ---------------------------------------------------------------------------
// Kernel 1: per-block partial sum/sumsq per action column. 128 blocks x 128
// rows; ~1us execution. Signals PDL completion after partials are written so
// the spline kernel (launched with ProgrammaticStreamSerialization) can pass
// its grid-dependency sync early. Deterministic fixed-order reductions.
// ---------------------------------------------------------------------------
__global__ __launch_bounds__(256) void bn_partial(const float* __restrict__ x)
{
    const int tid = threadIdx.x;
    const int c4  = tid & 15;
    const int r   = tid >> 4;
    const int b   = blockIdx.x;

    const float4* px = reinterpret_cast<const float4*>(x)
                     + (size_t)(b * ROWS_PER_B1 + r) * (ACTIONS / 4) + c4;

    float4 v[8];
#pragma unroll
    for (int k = 0; k < 8; k++)
        v[k] = __ldg(px + (size_t)k * 16 * (ACTIONS / 4));   // +16 rows each

    float4 s = {0.f, 0.f, 0.f, 0.f};
    float4 q = {0.f, 0.f, 0.f, 0.f};
#pragma unroll
    for (int k = 0; k < 8; k++) {
        s.x += v[k].x; q.x += v[k].x * v[k].x;
        s.y += v[k].y; q.y += v[k].y * v[k].y;
        s.z += v[k].z; q.z += v[k].z * v[k].z;
        s.w += v[k].w; q.w += v[k].w * v[k].w;
    }

    __shared__ float4 ss[16][16];
    __shared__ float4 sq[16][16];
    ss[r][c4] = s;
    sq[r][c4] = q;
    __syncthreads();

    if (tid < ACTIONS) {
        const int c = tid, cc = c >> 2, ce = c & 3;
        float ts = 0.f, tq = 0.f;
#pragma unroll
        for (int r2 = 0; r2 < 16; r2++) {
            ts += reinterpret_cast<const float*>(&ss[r2][cc])[ce];
            tq += reinterpret_cast<const float*>(&sq[r2][cc])[ce];
        }
        g_psum[b][c] = ts;
        g_psq [b][c] = tq;
    }

    __threadfence();                          // partials visible device-wide
    cudaTriggerProgrammaticLaunchCompletion(); // release dependent spline grid
}

// ---------------------------------------------------------------------------
// Kernel 2 (fused): BN prologue + smem-staged spline, v7 = v5 geometry + PDL.
// v5 measured 27.7us AT its l1tex structural floor (per 4 pairs: 2 LDS.128
// crossbar 8cyc + STG.128 12cyc + issue/shfl ~ 24cyc); v6's occupancy
// experiment regressed -> floor confirmed. v7 reverts to the v5 shape and
// attacks the LAUNCH layer instead: PDL lets this kernel start while
// bn_partial runs; everything bn-independent (table staging, x loads)
// happens BEFORE cudaGridDependencySynchronize().
//  - 16.9KB staged table slice; bh = bin+1 row (xh = xl+1 always).
//  - lane (g,e4) holds F[m] = f(row0+8m+e4, a0+g), m=0..3; iter jb=8m+i:
//    fj = shfl(F[m], g*8+i) -- one SHFL, compile-time register index.
//  - one STG.128 (__stcs) of 512B contiguous output per warp-iter.
//  - Deterministic: fixed-order fold+butterfly prologue, bit-identical/block.
// ---------------------------------------------------------------------------
__global__ __launch_bounds__(256) void spline_v7(const float* __restrict__ x,
                                                 const float* __restrict__ emb,
                                                 const float* __restrict__ wgt,
                                                 const float* __restrict__ bias,
                                                 float* __restrict__ out)
{
    __shared__ __align__(16) float s_tab[NBINS * A_PER_B * EMB]; // [bin][a][e]
    __shared__ float s_sc[A_PER_B];
    __shared__ float s_sh[A_PER_B];

    const int tid  = threadIdx.x;
    const int lane = tid & 31;
    const int w    = tid >> 5;                 // warp 0..7
    const int a0   = blockIdx.y * A_PER_B;
    const int row0 = blockIdx.x * R_PER_B + w * 32;

    const int g  = lane >> 3;                  // pair group 0..3 (action)
    const int e4 = lane & 7;                   // float4 slot within EMB
    const int g8 = g << 3;

    // ---- bn-independent work first (overlaps bn_partial via PDL) ----
    // stage table slice: bins 0..32, this block's 4 actions (1056 float4)
    {
        float4* st4 = reinterpret_cast<float4*>(s_tab);
        const float4* e4p = reinterpret_cast<const float4*>(emb);
        for (int i = tid; i < NBINS * A_PER_B * 8; i += 256) {
            const int bin = i >> 5;
            const int a   = (i >> 3) & 3;
            const int ee  = i & 7;
            st4[i] = __ldg(e4p + ((size_t)bin * ACTIONS + a0 + a) * 8 + ee);
        }
    }
    // x loads in F-layout: xv[m] for rows row0+8m+e4, action a0+g
    float xv[4];
    {
        const float* xp = x + (size_t)(row0 + e4) * ACTIONS + a0 + g;
#pragma unroll
        for (int m = 0; m < 4; m++)
            xv[m] = __ldg(xp + (size_t)m * 8 * ACTIONS);
    }

    // ---- wait for bn_partial's partials (PDL grid dependency) ----
    cudaGridDependencySynchronize();

    // ---- BN finalize: 4 actions x 128 partials (fold 4, butterfly 32) ----
    if (tid < 128) {
        const int ai = tid >> 5;
        const int p  = tid & 31;
        float s = (g_psum[p][a0 + ai] + g_psum[p + 32][a0 + ai])
                + (g_psum[p + 64][a0 + ai] + g_psum[p + 96][a0 + ai]);
        float q = (g_psq [p][a0 + ai] + g_psq [p + 32][a0 + ai])
                + (g_psq [p + 64][a0 + ai] + g_psq [p + 96][a0 + ai]);
#pragma unroll
        for (int off = 16; off > 0; off >>= 1) {
            s += __shfl_xor_sync(0xffffffffu, s, off);
            q += __shfl_xor_sync(0xffffffffu, q, off);
        }
        if (p == 0) {
            const float inv_n = 1.0f / (float)N_ROWS;
            float mean = s * inv_n;
            float var  = fmaf(-mean, mean, q * inv_n);
            float sc   = wgt[a0 + ai] * rsqrtf(var + EPSF);
            s_sc[ai] = sc;
            s_sh[ai] = fmaf(-mean, sc, bias[a0 + ai]);
        }
    }
    __syncthreads();

    // ---- tanh in F-layout ----
    const float sc = s_sc[g];
    const float sh = s_sh[g];
    float F[4];
#pragma unroll
    for (int m = 0; m < 4; m++) {
        float t = tanhf(fmaf(xv[m], sc, sh));
        t = fminf(fmaxf(t, -1.0f + 1e-5f), 1.0f - 1e-5f);
        F[m] = t * (float)DELTA;               // exact pow2 scale
    }

    const float4* tab4 = reinterpret_cast<const float4*>(s_tab);
    float4* out4 = reinterpret_cast<float4*>(out) + (size_t)g8 + e4;

    // ---- main loop: 32 rows/warp, one row (4 pairs) per iter, full unroll ----
#pragma unroll
    for (int m = 0; m < 4; m++) {
#pragma unroll
        for (int i = 0; i < 8; i++) {
            const int jb = m * 8 + i;
            const float fj = __shfl_sync(0xffffffffu, F[m], g8 + i);

            const float xlf = floorf(fj);
            const float wh  = fj - xlf;        // = DELTA*(t-xl), exact
            const float wl  = 1.0f - wh;       // = DELTA*(xh-t)
            const int   bin = (int)xlf + DELTA;    // 0..31

            const float4* p = tab4 + ((bin * A_PER_B + g) << 3) + e4;
            const float4 bl = p[0];
            const float4 bh = p[A_PER_B * 8];  // bin+1: +4 actions * 8 f4

            float4 h;
            h.x = bh.x * wh + bl.x * wl;
            h.y = bh.y * wh + bl.y * wl;
            h.z = bh.z * wh + bl.z * wl;
            h.w = bh.w * wh + bl.w * wl;

            // 32 lanes -> 512B contiguous: (row, a0..a0+3, all EMB)
            __stcs(out4 + ((size_t)(row0 + jb) * ACTIONS + a0) * 8, h);
        }
    }
}

// ---------------------------------------------------------------------------
// Launch: x, bn_weight, bn_bias, emb_table  ->  out [n, ACTIONS, EMB] fp32
// spline_v7 launched with ProgrammaticStreamSerialization (PDL): it starts
// while bn_partial runs, overlapping table staging + x loads with the BN
// partial pass; its gridsync gates only the partial-dependent part.
// ---------------------------------------------------------------------------
extern "C" void kernel_launch(void* const* d_in, const int* in_sizes, int n_in,
                              void* d_out, int out_size)
{
    const float* x    = (const float*)d_in[0];
    const float* wgt  = (const float*)d_in[1];
    const float* bias = (const float*)d_in[2];
    const float* emb  = (const float*)d_in[3];
    float* out        = (float*)d_out;

    bn_partial<<<NB1, 256>>>(x);

    cudaLaunchConfig_t cfg = {};
    cfg.gridDim  = dim3(N_ROWS / R_PER_B, ACTIONS / A_PER_B, 1);  // (64,16)
    cfg.blockDim = dim3(256, 1, 1);
    cfg.dynamicSmemBytes = 0;
    cudaLaunchAttribute attrs[1];
    attrs[0].id = cudaLaunchAttributeProgrammaticStreamSerialization;
    attrs[0].val.programmaticStreamSerializationAllowed = 1;
    cfg.attrs = attrs;
    cfg.numAttrs = 1;
    cudaLaunchKernelEx(&cfg, spline_v7, x, emb, wgt, bias, out);
}

// round 17
// speedup vs baseline: 1.1160x; 1.1160x over previous
#include <cuda_runtime.h>
#include <math.h>

#define N_ROWS   16384
#define ACTIONS  64
#define EMB      32
#define DELTA    16
#define EPSF     1e-5f

#define A_PER_B  4                        // actions per block
#define R_PER_B  256                      // rows per block
#define GRID_X   (N_ROWS / R_PER_B)       // 64
#define GRID_Y   (ACTIONS / A_PER_B)      // 16  -> 1024 blocks total
#define NBINS    33                       // staged bins (bl 0..31, bh needs +1)

// 1024 blocks <= 148 SMs * 8 blocks/SM (forced by __launch_bounds__(256,8);
// 21.3KB smem*8=170<=228KB; 2048 thr/SM) -> whole grid co-resident in wave 1,
// so the per-group spin barrier below cannot deadlock.

// Scratch + barrier state (device globals zero-init at load; self-reset each
// launch by the last departer, so graph replays always see zeros).
__device__ float g_ps[GRID_Y][GRID_X][A_PER_B];
__device__ float g_pq[GRID_Y][GRID_X][A_PER_B];
__device__ int   g_arrive[GRID_Y];
__device__ int   g_depart[GRID_Y];

// ---------------------------------------------------------------------------
// Single fused kernel: per-block stats partial -> per-group resident-grid
// barrier -> BN finalize -> v5 spline main loop (measured 27.7us floor).
// Replaces the bn_partial kernel + launch gap (~5.1us) with ~1.5us of
// in-kernel work. x is read once (stats tile == spline tile).
// Deterministic: all reductions fixed-order; atomics only count arrivals.
// ---------------------------------------------------------------------------
__global__ __launch_bounds__(256, 8)
void spline_fused1(const float* __restrict__ x,
                   const float* __restrict__ emb,
                   const float* __restrict__ wgt,
                   const float* __restrict__ bias,
                   float* __restrict__ out)
{
    __shared__ __align__(16) float s_tab[NBINS * A_PER_B * EMB]; // 16.9KB
    __shared__ __align__(16) float4 tf[256];                     // 4KB park/transpose
    __shared__ float4 sw_s[8], sw_q[8];
    __shared__ float  s_sc[A_PER_B], s_sh[A_PER_B];

    const int tid  = threadIdx.x;
    const int lane = tid & 31;
    const int w    = tid >> 5;
    const int bx   = blockIdx.x;
    const int by   = blockIdx.y;
    const int a0   = by * A_PER_B;
    const int row0 = bx * R_PER_B;

    // ---- 1. load x-tile: thread tid <-> row row0+tid, this block's 4 actions
    float4 xt = __ldg(reinterpret_cast<const float4*>(
                    x + (size_t)(row0 + tid) * ACTIONS + a0));

    // ---- 2. block stats partial (sum, sumsq per action), fixed order ----
    {
        float4 s = xt;
        float4 q;
        q.x = xt.x * xt.x; q.y = xt.y * xt.y;
        q.z = xt.z * xt.z; q.w = xt.w * xt.w;
#pragma unroll
        for (int off = 16; off > 0; off >>= 1) {
            s.x += __shfl_xor_sync(0xffffffffu, s.x, off);
            s.y += __shfl_xor_sync(0xffffffffu, s.y, off);
            s.z += __shfl_xor_sync(0xffffffffu, s.z, off);
            s.w += __shfl_xor_sync(0xffffffffu, s.w, off);
            q.x += __shfl_xor_sync(0xffffffffu, q.x, off);
            q.y += __shfl_xor_sync(0xffffffffu, q.y, off);
            q.z += __shfl_xor_sync(0xffffffffu, q.z, off);
            q.w += __shfl_xor_sync(0xffffffffu, q.w, off);
        }
        if (lane == 0) { sw_s[w] = s; sw_q[w] = q; }
    }
    tf[tid] = xt;                       // park xt in smem (keep regs at 32)
    __syncthreads();

    if (tid == 0) {
        float4 s = sw_s[0], q = sw_q[0];
#pragma unroll
        for (int k = 1; k < 8; k++) {
            s.x += sw_s[k].x; s.y += sw_s[k].y; s.z += sw_s[k].z; s.w += sw_s[k].w;
            q.x += sw_q[k].x; q.y += sw_q[k].y; q.z += sw_q[k].z; q.w += sw_q[k].w;
        }
        g_ps[by][bx][0] = s.x; g_ps[by][bx][1] = s.y;
        g_ps[by][bx][2] = s.z; g_ps[by][bx][3] = s.w;
        g_pq[by][bx][0] = q.x; g_pq[by][bx][1] = q.y;
        g_pq[by][bx][2] = q.z; g_pq[by][bx][3] = q.w;
        __threadfence();                 // release partials
        atomicAdd(&g_arrive[by], 1);
    }

    // ---- 3. stage table slice (overlaps other blocks' stats/arrivals) ----
    {
        float4* st4 = reinterpret_cast<float4*>(s_tab);
        const float4* e4p = reinterpret_cast<const float4*>(emb);
        for (int i = tid; i < NBINS * A_PER_B * 8; i += 256) {
            const int bin = i >> 5;
            const int a   = (i >> 3) & 3;
            const int ee  = i & 7;
            st4[i] = __ldg(e4p + ((size_t)bin * ACTIONS + a0 + a) * 8 + ee);
        }
    }

    // ---- 4. per-group barrier: wait for all 64 row-blocks of this group ----
    if (tid == 0) {
        while (*((volatile int*)&g_arrive[by]) != GRID_X)
            __nanosleep(64);
    }
    __syncthreads();

    // BN finalize: 4 actions x 64 partials (fold 2, butterfly 32), via L2
    if (tid < 128) {
        const int ai = tid >> 5;
        const int p  = tid & 31;
        float s = __ldcg(&g_ps[by][p][ai]) + __ldcg(&g_ps[by][p + 32][ai]);
        float q = __ldcg(&g_pq[by][p][ai]) + __ldcg(&g_pq[by][p + 32][ai]);
#pragma unroll
        for (int off = 16; off > 0; off >>= 1) {
            s += __shfl_xor_sync(0xffffffffu, s, off);
            q += __shfl_xor_sync(0xffffffffu, q, off);
        }
        if (p == 0) {
            const float inv_n = 1.0f / (float)N_ROWS;
            float mean = s * inv_n;
            float var  = fmaf(-mean, mean, q * inv_n);
            float sc   = wgt[a0 + ai] * rsqrtf(var + EPSF);
            s_sc[ai] = sc;
            s_sh[ai] = fmaf(-mean, sc, bias[a0 + ai]);
        }
    }
    __syncthreads();

    // ---- 5. tanh on parked xt, then smem transpose to F-layout ----
    xt = tf[tid];
    {
        float4 t4;
        float t;
        t = tanhf(fmaf(xt.x, s_sc[0], s_sh[0]));
        t4.x = fminf(fmaxf(t, -1.0f + 1e-5f), 1.0f - 1e-5f) * (float)DELTA;
        t = tanhf(fmaf(xt.y, s_sc[1], s_sh[1]));
        t4.y = fminf(fmaxf(t, -1.0f + 1e-5f), 1.0f - 1e-5f) * (float)DELTA;
        t = tanhf(fmaf(xt.z, s_sc[2], s_sh[2]));
        t4.z = fminf(fmaxf(t, -1.0f + 1e-5f), 1.0f - 1e-5f) * (float)DELTA;
        t = tanhf(fmaf(xt.w, s_sc[3], s_sh[3]));
        t4.w = fminf(fmaxf(t, -1.0f + 1e-5f), 1.0f - 1e-5f) * (float)DELTA;
        __syncthreads();                 // everyone done reading tf as xt-park
        tf[tid] = t4;                    // tf[row_local] = f of (row, 4 actions)
    }
    __syncthreads();

    const int g  = lane >> 3;            // pair group 0..3 (action)
    const int e4 = lane & 7;             // float4 slot within EMB
    const int g8 = g << 3;

    // F[m] = f(row0 + w*32 + 8m + e4, a0 + g)  (conflict-free scalar LDS)
    float F[4];
    {
        const float* tfs = reinterpret_cast<const float*>(tf + w * 32);
#pragma unroll
        for (int m = 0; m < 4; m++)
            F[m] = tfs[(8 * m + e4) * 4 + g];
    }

    const float4* tab4 = reinterpret_cast<const float4*>(s_tab);
    float4* out4 = reinterpret_cast<float4*>(out) + (size_t)g8 + e4;
    const int wrow0 = row0 + w * 32;

    // ---- 6. main loop: identical to v5 (27.7us measured floor) ----
#pragma unroll
    for (int m = 0; m < 4; m++) {
#pragma unroll
        for (int i = 0; i < 8; i++) {
            const int jb = m * 8 + i;
            const float fj = __shfl_sync(0xffffffffu, F[m], g8 + i);

            const float xlf = floorf(fj);
            const float wh  = fj - xlf;          // = DELTA*(t-xl), exact
            const float wl  = 1.0f - wh;         // = DELTA*(xh-t)
            const int   bin = (int)xlf + DELTA;  // 0..31

            const float4* p = tab4 + ((bin * A_PER_B + g) << 3) + e4;
            const float4 bl = p[0];
            const float4 bh = p[A_PER_B * 8];    // bin+1 row

            float4 h;
            h.x = bh.x * wh + bl.x * wl;
            h.y = bh.y * wh + bl.y * wl;
            h.z = bh.z * wh + bl.z * wl;
            h.w = bh.w * wh + bl.w * wl;

            __stcs(out4 + ((size_t)(wrow0 + jb) * ACTIONS + a0) * 8, h);
        }
    }

    // ---- 7. self-cleaning barrier state for graph replays ----
    if (tid == 0) {
        int t = atomicAdd(&g_depart[by], 1);
        if (t == GRID_X - 1) {           // last departer: everyone passed spin
            g_arrive[by] = 0;
            g_depart[by] = 0;
        }
    }
}

// ---------------------------------------------------------------------------
// Launch: x, bn_weight, bn_bias, emb_table  ->  out [n, ACTIONS, EMB] fp32
// Single launch; no inter-kernel gap.
// ---------------------------------------------------------------------------
extern "C" void kernel_launch(void* const* d_in, const int* in_sizes, int n_in,
                              void* d_out, int out_size)
{
    const float* x    = (const float*)d_in[0];
    const float* wgt  = (const float*)d_in[1];
    const float* bias = (const float*)d_in[2];
    const float* emb  = (const float*)d_in[3];
    float* out        = (float*)d_out;

    dim3 grid(GRID_X, GRID_Y);           // (64, 16) = 1024 blocks, 1 wave
    spline_fused1<<<grid, 256>>>(x, emb, wgt, bias, out);
}